// round 8
// baseline (speedup 1.0000x reference)
#include <cuda_runtime.h>

// Problem constants (fixed by the reference)
#define E_EDGES   2000000
#define NSEG      100000
#define INV_TEMP  0.125f   // 1 / TEMPERATURE

// Scratch (no allocs allowed): per-segment denominators.
// Zero-initialized at module load; reset_kernel re-zeroes after K2 each call,
// so every kernel_launch sees zeros -> deterministic across graph replays.
__device__ float g_sum[NSEG];

// ---------------------------------------------------------------------------
// Index dtype detection: reference asks int64 but default JAX canonicalizes to
// int32. Probe 8 bytes at int64-position E/4: sorted uniform over [0,100000)
// -> int64 hi-word there is 0; int32 interpretation puts ~50000 there.
// ---------------------------------------------------------------------------
__device__ __forceinline__ bool index_is_64(const void* __restrict__ idx) {
    const int2 probe = __ldg(&((const int2*)idx)[E_EDGES / 4]);
    return probe.y == 0;
}

// ---------------------------------------------------------------------------
// K1 (at HBM roofline — do not touch): 4 edges per warp, 8 lanes per edge,
// 4 front-batched LDG.128 per thread (MLP_p1=4, regs 26, occ ~90%, DRAM ~88%).
// q/k streamed (__ldcs); out stored __stcg and index read __ldg so both stay
// L2-resident (L2 = 126 MB) for K2's re-read.
// ---------------------------------------------------------------------------
__global__ void __launch_bounds__(256)
score_exp_kernel(const float4* __restrict__ q,
                 const float4* __restrict__ k,
                 const void*   __restrict__ index,
                 float*        __restrict__ out) {
    const int tid  = blockIdx.x * blockDim.x + threadIdx.x;
    const int warp = tid >> 5;
    const int lane = tid & 31;
    const int g    = lane >> 3;       // edge within warp (0..3)
    const int sub  = lane & 7;        // lane within 8-group

    const long long e    = (long long)warp * 4 + g;
    const long long base = e * 16;    // float4 index of row start

    // Front-batched independent streaming loads (MLP_p1 = 4):
    const float4 qa = __ldcs(&q[base + sub]);
    const float4 qb = __ldcs(&q[base + sub + 8]);
    const float4 ka = __ldcs(&k[base + sub]);
    const float4 kb = __ldcs(&k[base + sub + 8]);

    float d0 = qa.x * ka.x + qa.y * ka.y + qa.z * ka.z + qa.w * ka.w;
    float d1 = qb.x * kb.x + qb.y * kb.y + qb.z * kb.z + qb.w * kb.w;
    float d  = d0 + d1;

    // Reduce within the 8-lane group (3 shuffles)
    d += __shfl_xor_sync(0xFFFFFFFFu, d, 4);
    d += __shfl_xor_sync(0xFFFFFFFFu, d, 2);
    d += __shfl_xor_sync(0xFFFFFFFFu, d, 1);

    // Every lane in group g now has edge g's score; exponentiate (MUFU).
    const float ex = __expf(d * INV_TEMP);

    // Gather the 4 group results to lane 0.
    const float e1 = __shfl_sync(0xFFFFFFFFu, ex, 8);
    const float e2 = __shfl_sync(0xFFFFFFFFu, ex, 16);
    const float e3 = __shfl_sync(0xFFFFFFFFu, ex, 24);

    if (lane == 0) {
        // One 16B store for 4 numerators; evict-normal -> stays in L2 for K2.
        __stcg(reinterpret_cast<float4*>(out) + warp, make_float4(ex, e1, e2, e3));

        // One vector load for 4 segment ids; cached -> L2-resident for K2.
        int s0, s1, s2, s3;
        if (index_is_64(index)) {
            const longlong2 sa = __ldg(reinterpret_cast<const longlong2*>(index) + warp * 2);
            const longlong2 sb = __ldg(reinterpret_cast<const longlong2*>(index) + warp * 2 + 1);
            s0 = (int)sa.x; s1 = (int)sa.y; s2 = (int)sb.x; s3 = (int)sb.y;
        } else {
            const int4 sv = __ldg(reinterpret_cast<const int4*>(index) + warp);
            s0 = sv.x; s1 = sv.y; s2 = sv.z; s3 = sv.w;
        }

        // Run-merge (index sorted -> usually one REDG per 4 edges).
        float acc = ex;
        int   cur = s0;
        if (s1 == cur) acc += e1; else { atomicAdd(&g_sum[cur], acc); cur = s1; acc = e1; }
        if (s2 == cur) acc += e2; else { atomicAdd(&g_sum[cur], acc); cur = s2; acc = e2; }
        if (s3 == cur) acc += e3; else { atomicAdd(&g_sum[cur], acc); cur = s3; acc = e3; }
        atomicAdd(&g_sum[cur], acc);
    }
}

// ---------------------------------------------------------------------------
// K2: normalize = divide by segment denominator (g_sum is L2-hot from K1's
// atomics; __fdividef is MUFU-cheap and K2 is latency-bound on the gathers).
// 4 edges/thread, 1954 blocks; out/index loads are L2 hits.
// ---------------------------------------------------------------------------
__global__ void __launch_bounds__(256)
normalize_kernel(const void* __restrict__ index,
                 float*      __restrict__ out) {
    const int t = blockIdx.x * blockDim.x + threadIdx.x;
    const int i = t * 4;
    if (i >= E_EDGES) return;

    const bool is64 = index_is_64(index);

    float4 o = __ldg(reinterpret_cast<const float4*>(out) + t);

    int s0, s1, s2, s3;
    if (!is64) {
        const int4 sv = __ldg(reinterpret_cast<const int4*>(index) + t);
        s0 = sv.x; s1 = sv.y; s2 = sv.z; s3 = sv.w;
    } else {
        const longlong2 sa = __ldg(reinterpret_cast<const longlong2*>(index) + t * 2);
        const longlong2 sb = __ldg(reinterpret_cast<const longlong2*>(index) + t * 2 + 1);
        s0 = (int)sa.x; s1 = (int)sa.y; s2 = (int)sb.x; s3 = (int)sb.y;
    }

    o.x = __fdividef(o.x, __ldg(&g_sum[s0]));
    o.y = __fdividef(o.y, __ldg(&g_sum[s1]));
    o.z = __fdividef(o.z, __ldg(&g_sum[s2]));
    o.w = __fdividef(o.w, __ldg(&g_sum[s3]));
    __stcs(reinterpret_cast<float4*>(out) + t, o);
}

// ---------------------------------------------------------------------------
// K3: reset denominators for the next graph replay (runs after K2; stream
// order guarantees completion before the next call's K1). 400 KB of zeros,
// 8 segments/thread, 49 blocks.
// ---------------------------------------------------------------------------
__global__ void __launch_bounds__(256)
reset_kernel() {
    const int i = blockIdx.x * blockDim.x + threadIdx.x;
    if (i >= NSEG / 8) return;
    const float4 z = make_float4(0.f, 0.f, 0.f, 0.f);
    reinterpret_cast<float4*>(g_sum)[i * 2]     = z;
    reinterpret_cast<float4*>(g_sum)[i * 2 + 1] = z;
}

// ---------------------------------------------------------------------------
// Launch. Inputs in metadata order: q [E*64 f32], k [E*64 f32], index [E].
// Output: E f32. Three kernel nodes: K1 -> K2 -> reset.
// ---------------------------------------------------------------------------
extern "C" void kernel_launch(void* const* d_in, const int* in_sizes, int n_in,
                              void* d_out, int out_size) {
    const float4* q   = (const float4*)d_in[0];
    const float4* k   = (const float4*)d_in[1];
    const void*   idx = d_in[2];
    float*        out = (float*)d_out;

    // K1: 4 edges per warp -> E*8 threads (62500 blocks)
    {
        const long long total_threads = (long long)E_EDGES * 8;
        const int blocks = (int)(total_threads / 256);
        score_exp_kernel<<<blocks, 256>>>(q, k, idx, out);
    }

    // K2: 4 edges per thread (500000 threads, 1954 blocks)
    {
        const int threads = E_EDGES / 4;
        normalize_kernel<<<(threads + 255) / 256, 256>>>(idx, out);
    }

    // K3: reset denominators for next replay (12500 threads, 49 blocks)
    reset_kernel<<<(NSEG / 8 + 255) / 256, 256>>>();
}

// round 9
// speedup vs baseline: 1.0017x; 1.0017x over previous
#include <cuda_runtime.h>

// Problem constants (fixed by the reference)
#define E_EDGES   2000000
#define NSEG      100000
#define INV_TEMP  0.125f   // 1 / TEMPERATURE

// Scratch (no allocs allowed): denominators + reciprocals.
// g_sum is zero-initialized at module load; rcp_kernel re-zeroes it every
// call, so each kernel_launch sees zeros -> deterministic across replays.
__device__ float g_sum[NSEG];
__device__ float g_rcp[NSEG];

// ---------------------------------------------------------------------------
// Index dtype detection: reference asks int64 but default JAX canonicalizes to
// int32. Probe 8 bytes at int64-position E/4: sorted uniform over [0,100000)
// -> int64 hi-word there is 0; int32 interpretation puts ~50000 there.
// ---------------------------------------------------------------------------
__device__ __forceinline__ bool index_is_64(const void* __restrict__ idx) {
    const int2 probe = __ldg(&((const int2*)idx)[E_EDGES / 4]);
    return probe.y == 0;
}

// ---------------------------------------------------------------------------
// K1 (at HBM roofline): 4 edges per warp, 8 lanes per edge, 4 front-batched
// LDG.128 per thread (MLP_p1=4, regs 26, occ ~90%, DRAM ~88%, 6.95 TB/s).
// q/k streamed (__ldcs); out stored __stcg and index read __ldg so both stay
// L2-resident (L2 = 126 MB) for K2's re-read.
// ---------------------------------------------------------------------------
__global__ void __launch_bounds__(256)
score_exp_kernel(const float4* __restrict__ q,
                 const float4* __restrict__ k,
                 const void*   __restrict__ index,
                 float*        __restrict__ out) {
    const int tid  = blockIdx.x * blockDim.x + threadIdx.x;
    const int warp = tid >> 5;
    const int lane = tid & 31;
    const int g    = lane >> 3;       // edge within warp (0..3)
    const int sub  = lane & 7;        // lane within 8-group

    const long long e    = (long long)warp * 4 + g;
    const long long base = e * 16;    // float4 index of row start

    // Front-batched independent streaming loads (MLP_p1 = 4):
    const float4 qa = __ldcs(&q[base + sub]);
    const float4 qb = __ldcs(&q[base + sub + 8]);
    const float4 ka = __ldcs(&k[base + sub]);
    const float4 kb = __ldcs(&k[base + sub + 8]);

    float d0 = qa.x * ka.x + qa.y * ka.y + qa.z * ka.z + qa.w * ka.w;
    float d1 = qb.x * kb.x + qb.y * kb.y + qb.z * kb.z + qb.w * kb.w;
    float d  = d0 + d1;

    // Reduce within the 8-lane group (3 shuffles)
    d += __shfl_xor_sync(0xFFFFFFFFu, d, 4);
    d += __shfl_xor_sync(0xFFFFFFFFu, d, 2);
    d += __shfl_xor_sync(0xFFFFFFFFu, d, 1);

    // Every lane in group g now has edge g's score; exponentiate (MUFU).
    const float ex = __expf(d * INV_TEMP);

    // Gather the 4 group results to lane 0.
    const float e1 = __shfl_sync(0xFFFFFFFFu, ex, 8);
    const float e2 = __shfl_sync(0xFFFFFFFFu, ex, 16);
    const float e3 = __shfl_sync(0xFFFFFFFFu, ex, 24);

    if (lane == 0) {
        // One 16B store for 4 numerators; evict-normal -> stays in L2 for K2.
        __stcg(reinterpret_cast<float4*>(out) + warp, make_float4(ex, e1, e2, e3));

        // One vector load for 4 segment ids; cached -> L2-resident for K2.
        int s0, s1, s2, s3;
        if (index_is_64(index)) {
            const longlong2 sa = __ldg(reinterpret_cast<const longlong2*>(index) + warp * 2);
            const longlong2 sb = __ldg(reinterpret_cast<const longlong2*>(index) + warp * 2 + 1);
            s0 = (int)sa.x; s1 = (int)sa.y; s2 = (int)sb.x; s3 = (int)sb.y;
        } else {
            const int4 sv = __ldg(reinterpret_cast<const int4*>(index) + warp);
            s0 = sv.x; s1 = sv.y; s2 = sv.z; s3 = sv.w;
        }

        // Run-merge (index sorted -> usually one REDG per 4 edges).
        float acc = ex;
        int   cur = s0;
        if (s1 == cur) acc += e1; else { atomicAdd(&g_sum[cur], acc); cur = s1; acc = e1; }
        if (s2 == cur) acc += e2; else { atomicAdd(&g_sum[cur], acc); cur = s2; acc = e2; }
        if (s3 == cur) acc += e3; else { atomicAdd(&g_sum[cur], acc); cur = s3; acc = e3; }
        atomicAdd(&g_sum[cur], acc);
    }
}

// ---------------------------------------------------------------------------
// K1.5: reciprocal of denominators + self-reset of g_sum for the next replay.
// 8 segments/thread -> 12500 threads, 49 blocks, single wave.
// ---------------------------------------------------------------------------
__global__ void __launch_bounds__(256)
rcp_kernel() {
    const int i = blockIdx.x * blockDim.x + threadIdx.x;
    if (i >= NSEG / 8) return;
    float4 sa = reinterpret_cast<float4*>(g_sum)[i * 2];
    float4 sb = reinterpret_cast<float4*>(g_sum)[i * 2 + 1];
    float4 ra, rb;
    ra.x = __fdividef(1.0f, sa.x);
    ra.y = __fdividef(1.0f, sa.y);
    ra.z = __fdividef(1.0f, sa.z);
    ra.w = __fdividef(1.0f, sa.w);
    rb.x = __fdividef(1.0f, sb.x);
    rb.y = __fdividef(1.0f, sb.y);
    rb.z = __fdividef(1.0f, sb.z);
    rb.w = __fdividef(1.0f, sb.w);
    reinterpret_cast<float4*>(g_rcp)[i * 2]     = ra;
    reinterpret_cast<float4*>(g_rcp)[i * 2 + 1] = rb;
    const float4 z = make_float4(0.f, 0.f, 0.f, 0.f);
    reinterpret_cast<float4*>(g_sum)[i * 2]     = z;
    reinterpret_cast<float4*>(g_sum)[i * 2 + 1] = z;
}

// ---------------------------------------------------------------------------
// K2: normalize = multiply by reciprocal. 4 edges/thread, 1954 blocks.
// out/index are L2-resident from K1 -> loads are L2 hits; tail ~1.9 us total.
// ---------------------------------------------------------------------------
__global__ void __launch_bounds__(256)
normalize_kernel(const void* __restrict__ index,
                 float*      __restrict__ out) {
    const int t = blockIdx.x * blockDim.x + threadIdx.x;
    const int i = t * 4;
    if (i >= E_EDGES) return;

    const bool is64 = index_is_64(index);

    float4 o = __ldg(reinterpret_cast<const float4*>(out) + t);

    int s0, s1, s2, s3;
    if (!is64) {
        const int4 sv = __ldg(reinterpret_cast<const int4*>(index) + t);
        s0 = sv.x; s1 = sv.y; s2 = sv.z; s3 = sv.w;
    } else {
        const longlong2 sa = __ldg(reinterpret_cast<const longlong2*>(index) + t * 2);
        const longlong2 sb = __ldg(reinterpret_cast<const longlong2*>(index) + t * 2 + 1);
        s0 = (int)sa.x; s1 = (int)sa.y; s2 = (int)sb.x; s3 = (int)sb.y;
    }

    o.x *= __ldg(&g_rcp[s0]);
    o.y *= __ldg(&g_rcp[s1]);
    o.z *= __ldg(&g_rcp[s2]);
    o.w *= __ldg(&g_rcp[s3]);
    __stcs(reinterpret_cast<float4*>(out) + t, o);
}

// ---------------------------------------------------------------------------
// Launch. Inputs in metadata order: q [E*64 f32], k [E*64 f32], index [E].
// Output: E f32. Three kernel nodes: K1 -> rcp(+reset) -> K2.
// ---------------------------------------------------------------------------
extern "C" void kernel_launch(void* const* d_in, const int* in_sizes, int n_in,
                              void* d_out, int out_size) {
    const float4* q   = (const float4*)d_in[0];
    const float4* k   = (const float4*)d_in[1];
    const void*   idx = d_in[2];
    float*        out = (float*)d_out;

    // K1: 4 edges per warp -> E*8 threads (62500 blocks)
    {
        const long long total_threads = (long long)E_EDGES * 8;
        const int blocks = (int)(total_threads / 256);
        score_exp_kernel<<<blocks, 256>>>(q, k, idx, out);
    }

    // K1.5: reciprocals + reset (12500 threads, 49 blocks)
    rcp_kernel<<<(NSEG / 8 + 255) / 256, 256>>>();

    // K2: 4 edges per thread (500000 threads, 1954 blocks)
    {
        const int threads = E_EDGES / 4;
        normalize_kernel<<<(threads + 255) / 256, 256>>>(idx, out);
    }
}

// round 10
// speedup vs baseline: 1.0061x; 1.0044x over previous
#include <cuda_runtime.h>

// Problem constants (fixed by the reference)
#define E_EDGES   2000000
#define NSEG      100000
#define INV_TEMP  0.125f   // 1 / TEMPERATURE

// Scratch (no allocs allowed): denominators + reciprocals.
// g_sum is zero-initialized at module load; rcp_kernel re-zeroes it every
// call, so each kernel_launch sees zeros -> deterministic across replays.
__device__ float g_sum[NSEG];
__device__ float g_rcp[NSEG];

// ---------------------------------------------------------------------------
// Index dtype detection: reference asks int64 but default JAX canonicalizes to
// int32. Probe 8 bytes at int64-position E/4: sorted uniform over [0,100000)
// -> int64 hi-word there is 0; int32 interpretation puts ~50000 there.
// ---------------------------------------------------------------------------
__device__ __forceinline__ bool index_is_64(const void* __restrict__ idx) {
    const int2 probe = __ldg(&((const int2*)idx)[E_EDGES / 4]);
    return probe.y == 0;
}

// ---------------------------------------------------------------------------
// K1 (at HBM roofline): 4 edges per warp, 8 lanes per edge, 4 front-batched
// LDG.128 per thread (MLP_p1=4, regs 26, occ ~90%, DRAM ~88%, ~7.0 TB/s).
// q/k streamed (__ldcs); out stored __stcg and index read __ldg so both stay
// L2-resident (L2 = 126 MB) for K2's re-read.
// Traffic model: 1.040 GB DRAM @ 7.0 TB/s = 148.6 us = measured duration.
// ---------------------------------------------------------------------------
__global__ void __launch_bounds__(256)
score_exp_kernel(const float4* __restrict__ q,
                 const float4* __restrict__ k,
                 const void*   __restrict__ index,
                 float*        __restrict__ out) {
    const int tid  = blockIdx.x * blockDim.x + threadIdx.x;
    const int warp = tid >> 5;
    const int lane = tid & 31;
    const int g    = lane >> 3;       // edge within warp (0..3)
    const int sub  = lane & 7;        // lane within 8-group

    const long long e    = (long long)warp * 4 + g;
    const long long base = e * 16;    // float4 index of row start

    // Front-batched independent streaming loads (MLP_p1 = 4):
    const float4 qa = __ldcs(&q[base + sub]);
    const float4 qb = __ldcs(&q[base + sub + 8]);
    const float4 ka = __ldcs(&k[base + sub]);
    const float4 kb = __ldcs(&k[base + sub + 8]);

    float d0 = qa.x * ka.x + qa.y * ka.y + qa.z * ka.z + qa.w * ka.w;
    float d1 = qb.x * kb.x + qb.y * kb.y + qb.z * kb.z + qb.w * kb.w;
    float d  = d0 + d1;

    // Reduce within the 8-lane group (3 shuffles)
    d += __shfl_xor_sync(0xFFFFFFFFu, d, 4);
    d += __shfl_xor_sync(0xFFFFFFFFu, d, 2);
    d += __shfl_xor_sync(0xFFFFFFFFu, d, 1);

    // Every lane in group g now has edge g's score; exponentiate (MUFU).
    const float ex = __expf(d * INV_TEMP);

    // Gather the 4 group results to lane 0.
    const float e1 = __shfl_sync(0xFFFFFFFFu, ex, 8);
    const float e2 = __shfl_sync(0xFFFFFFFFu, ex, 16);
    const float e3 = __shfl_sync(0xFFFFFFFFu, ex, 24);

    if (lane == 0) {
        // One 16B store for 4 numerators; evict-normal -> stays in L2 for K2.
        __stcg(reinterpret_cast<float4*>(out) + warp, make_float4(ex, e1, e2, e3));

        // One vector load for 4 segment ids; cached -> L2-resident for K2.
        int s0, s1, s2, s3;
        if (index_is_64(index)) {
            const longlong2 sa = __ldg(reinterpret_cast<const longlong2*>(index) + warp * 2);
            const longlong2 sb = __ldg(reinterpret_cast<const longlong2*>(index) + warp * 2 + 1);
            s0 = (int)sa.x; s1 = (int)sa.y; s2 = (int)sb.x; s3 = (int)sb.y;
        } else {
            const int4 sv = __ldg(reinterpret_cast<const int4*>(index) + warp);
            s0 = sv.x; s1 = sv.y; s2 = sv.z; s3 = sv.w;
        }

        // Run-merge (index sorted -> usually one REDG per 4 edges).
        float acc = ex;
        int   cur = s0;
        if (s1 == cur) acc += e1; else { atomicAdd(&g_sum[cur], acc); cur = s1; acc = e1; }
        if (s2 == cur) acc += e2; else { atomicAdd(&g_sum[cur], acc); cur = s2; acc = e2; }
        if (s3 == cur) acc += e3; else { atomicAdd(&g_sum[cur], acc); cur = s3; acc = e3; }
        atomicAdd(&g_sum[cur], acc);
    }
}

// ---------------------------------------------------------------------------
// K1.5: reciprocal of denominators + self-reset of g_sum for the next replay.
// 8 segments/thread -> 12500 threads, 49 blocks, single wave.
// ---------------------------------------------------------------------------
__global__ void __launch_bounds__(256)
rcp_kernel() {
    const int i = blockIdx.x * blockDim.x + threadIdx.x;
    if (i >= NSEG / 8) return;
    float4 sa = reinterpret_cast<float4*>(g_sum)[i * 2];
    float4 sb = reinterpret_cast<float4*>(g_sum)[i * 2 + 1];
    float4 ra, rb;
    ra.x = __fdividef(1.0f, sa.x);
    ra.y = __fdividef(1.0f, sa.y);
    ra.z = __fdividef(1.0f, sa.z);
    ra.w = __fdividef(1.0f, sa.w);
    rb.x = __fdividef(1.0f, sb.x);
    rb.y = __fdividef(1.0f, sb.y);
    rb.z = __fdividef(1.0f, sb.z);
    rb.w = __fdividef(1.0f, sb.w);
    reinterpret_cast<float4*>(g_rcp)[i * 2]     = ra;
    reinterpret_cast<float4*>(g_rcp)[i * 2 + 1] = rb;
    const float4 z = make_float4(0.f, 0.f, 0.f, 0.f);
    reinterpret_cast<float4*>(g_sum)[i * 2]     = z;
    reinterpret_cast<float4*>(g_sum)[i * 2 + 1] = z;
}

// ---------------------------------------------------------------------------
// K2: normalize = multiply by reciprocal. 4 edges/thread, 1954 blocks.
// out/index are L2-resident from K1 -> loads are L2 hits; tail ~1.9 us total.
// ---------------------------------------------------------------------------
__global__ void __launch_bounds__(256)
normalize_kernel(const void* __restrict__ index,
                 float*      __restrict__ out) {
    const int t = blockIdx.x * blockDim.x + threadIdx.x;
    const int i = t * 4;
    if (i >= E_EDGES) return;

    const bool is64 = index_is_64(index);

    float4 o = __ldg(reinterpret_cast<const float4*>(out) + t);

    int s0, s1, s2, s3;
    if (!is64) {
        const int4 sv = __ldg(reinterpret_cast<const int4*>(index) + t);
        s0 = sv.x; s1 = sv.y; s2 = sv.z; s3 = sv.w;
    } else {
        const longlong2 sa = __ldg(reinterpret_cast<const longlong2*>(index) + t * 2);
        const longlong2 sb = __ldg(reinterpret_cast<const longlong2*>(index) + t * 2 + 1);
        s0 = (int)sa.x; s1 = (int)sa.y; s2 = (int)sb.x; s3 = (int)sb.y;
    }

    o.x *= __ldg(&g_rcp[s0]);
    o.y *= __ldg(&g_rcp[s1]);
    o.z *= __ldg(&g_rcp[s2]);
    o.w *= __ldg(&g_rcp[s3]);
    __stcs(reinterpret_cast<float4*>(out) + t, o);
}

// ---------------------------------------------------------------------------
// Launch. Inputs in metadata order: q [E*64 f32], k [E*64 f32], index [E].
// Output: E f32. Three kernel nodes: K1 -> rcp(+reset) -> K2.
// ---------------------------------------------------------------------------
extern "C" void kernel_launch(void* const* d_in, const int* in_sizes, int n_in,
                              void* d_out, int out_size) {
    const float4* q   = (const float4*)d_in[0];
    const float4* k   = (const float4*)d_in[1];
    const void*   idx = d_in[2];
    float*        out = (float*)d_out;

    // K1: 4 edges per warp -> E*8 threads (62500 blocks)
    {
        const long long total_threads = (long long)E_EDGES * 8;
        const int blocks = (int)(total_threads / 256);
        score_exp_kernel<<<blocks, 256>>>(q, k, idx, out);
    }

    // K1.5: reciprocals + reset (12500 threads, 49 blocks)
    rcp_kernel<<<(NSEG / 8 + 255) / 256, 256>>>();

    // K2: 4 edges per thread (500000 threads, 1954 blocks)
    {
        const int threads = E_EDGES / 4;
        normalize_kernel<<<(threads + 255) / 256, 256>>>(idx, out);
    }
}